// round 2
// baseline (speedup 1.0000x reference)
#include <cuda_runtime.h>
#include <cuda_bf16.h>
#include <math.h>

#define Bz 16
#define Sz 512
#define Hz 512
#define Vz 10000
#define Gz 2048
#define NCTA 128

typedef unsigned long long ull;

__device__ __forceinline__ void fma2(ull& d, ull a, ull b) {
    asm("fma.rn.f32x2 %0, %1, %2, %0;" : "+l"(d) : "l"(a), "l"(b));
}

// ---- scratch (static device globals: no runtime allocation allowed) ----
__device__ float g_emb [Bz*Sz*Hz];
__device__ float g_xproj[Bz*Sz*Gz];
__device__ float g_hs0 [Bz*Sz*Hz];
__device__ float g_hs1 [Bz*Sz*Hz];
__device__ float g_hid [Bz*Sz*128];
__device__ float g_h   [2*Hz*Bz];        // double-buffered h, layout [u][b]
__device__ unsigned g_flag[2*NCTA];      // per-CTA progress flags (2 scans)

// ------------------------------------------------------------------
__global__ void reset_kernel() {
    if (threadIdx.x < 2*NCTA) g_flag[threadIdx.x] = 0u;
}

// emb[bs][h] = w_emb[h][src[bs]] + b_emb[h]
__global__ void embed_kernel(const int* __restrict__ src,
                             const float* __restrict__ w_emb,
                             const float* __restrict__ b_emb)
{
    int idx = blockIdx.x * 256 + threadIdx.x;
    if (idx >= Bz*Sz*Hz) return;
    int h  = idx & (Hz-1);
    int bs = idx >> 9;
    int v  = src[bs];
    g_emb[idx] = w_emb[h*Vz + v] + b_emb[h];
}

// ------------------------------------------------------------------
// C[M,N] = A[M,K] @ B[N,K]^T + bias (+bias2), optional relu.
// 128x128 tile, BK=16, 8x8 microtile via FFMA2 (A duplicated in SMEM).
#define AS_STR 268
#define BS_STR 140
__global__ void __launch_bounds__(256, 2)
gemm_nt(const float* __restrict__ A, const float* __restrict__ B,
        const float* __restrict__ bias, const float* __restrict__ bias2,
        float* __restrict__ C, int M, int N, int K, int relu)
{
    __shared__ float As[16*AS_STR];   // [k][2m]: every A value duplicated
    __shared__ float Bs[16*BS_STR];   // [k][n]

    const int n0 = blockIdx.x * 128;
    const int m0 = blockIdx.y * 128;
    const int tid = threadIdx.x;

    const int lr = tid >> 2;          // 0..63
    const int lc = (tid & 3) * 4;     // k offset 0,4,8,12

    const float* Ap0 = A + (size_t)(m0 + lr)      * K + lc;
    const float* Ap1 = A + (size_t)(m0 + lr + 64) * K + lc;
    const float* Bp0 = B + (size_t)(n0 + lr)      * K + lc;
    const float* Bp1 = B + (size_t)(n0 + lr + 64) * K + lc;
    const bool bv0 = (n0 + lr)      < N;
    const bool bv1 = (n0 + lr + 64) < N;

    const int tx = tid & 15;          // n microtile (8 cols)
    const int ty = tid >> 4;          // m microtile (8 rows)

    ull acc[8][4];
#pragma unroll
    for (int i = 0; i < 8; i++)
#pragma unroll
        for (int j = 0; j < 4; j++) acc[i][j] = 0ull;

    for (int kb = 0; kb < K; kb += 16) {
        float4 a0 = *(const float4*)(Ap0 + kb);
        float4 a1 = *(const float4*)(Ap1 + kb);
        float4 b0 = bv0 ? *(const float4*)(Bp0 + kb) : make_float4(0,0,0,0);
        float4 b1 = bv1 ? *(const float4*)(Bp1 + kb) : make_float4(0,0,0,0);
        __syncthreads();
        {
            float av0[4] = {a0.x, a0.y, a0.z, a0.w};
            float av1[4] = {a1.x, a1.y, a1.z, a1.w};
            float bw0[4] = {b0.x, b0.y, b0.z, b0.w};
            float bw1[4] = {b1.x, b1.y, b1.z, b1.w};
#pragma unroll
            for (int j = 0; j < 4; j++) {
                float* as = As + (lc + j) * AS_STR;
                *(float2*)(as + 2*lr)       = make_float2(av0[j], av0[j]);
                *(float2*)(as + 2*lr + 128) = make_float2(av1[j], av1[j]);
                float* bs = Bs + (lc + j) * BS_STR;
                bs[lr]      = bw0[j];
                bs[lr + 64] = bw1[j];
            }
        }
        __syncthreads();
#pragma unroll
        for (int k = 0; k < 16; k++) {
            const float* as = As + k * AS_STR + 16 * ty;
            const float* bs = Bs + k * BS_STR + 8 * tx;
            ulonglong2 a01 = *(const ulonglong2*)(as);      // (a0,a0),(a1,a1)
            ulonglong2 a23 = *(const ulonglong2*)(as + 4);
            ulonglong2 a45 = *(const ulonglong2*)(as + 8);
            ulonglong2 a67 = *(const ulonglong2*)(as + 12);
            ulonglong2 b01 = *(const ulonglong2*)(bs);      // (b0,b1),(b2,b3)
            ulonglong2 b23 = *(const ulonglong2*)(bs + 4);
            ull av[8] = {a01.x, a01.y, a23.x, a23.y, a45.x, a45.y, a67.x, a67.y};
            ull bv[4] = {b01.x, b01.y, b23.x, b23.y};
#pragma unroll
            for (int mi = 0; mi < 8; mi++)
#pragma unroll
                for (int np = 0; np < 4; np++)
                    fma2(acc[mi][np], av[mi], bv[np]);
        }
    }

#pragma unroll
    for (int np = 0; np < 4; np++) {
        int n = n0 + tx*8 + 2*np;
        float bb0 = 0.f, bb1 = 0.f;
        bool v0 = n < N, v1 = (n+1) < N;
        if (v0) bb0 = bias[n]   + (bias2 ? bias2[n]   : 0.f);
        if (v1) bb1 = bias[n+1] + (bias2 ? bias2[n+1] : 0.f);
#pragma unroll
        for (int mi = 0; mi < 8; mi++) {
            int m = m0 + ty*8 + mi;
            float2 f = *(float2*)&acc[mi][np];
            if (v0) {
                float v = f.x + bb0;
                if (relu) v = fmaxf(v, 0.f);
                C[(size_t)m * N + n] = v;
            }
            if (v1) {
                float v = f.y + bb1;
                if (relu) v = fmaxf(v, 0.f);
                C[(size_t)m * N + n + 1] = v;
            }
        }
    }
}

// ------------------------------------------------------------------
// Persistent LSTM scan. 128 CTAs x 256 threads, each CTA owns 4 hidden
// units (16 gate rows). Flag-array grid barrier; FFMA2 inner loop with
// batch-duplicated h in SMEM; xproj prefetched under the barrier wait.
__global__ void __launch_bounds__(256)
lstm_scan(const float* __restrict__ xproj, const float* __restrict__ w_hh,
          float* __restrict__ hs, unsigned* __restrict__ flags)
{
    extern __shared__ float sm[];
    float* w_s   = sm;                 // [512][16]  k-major x local-gate
    float* hd_s  = sm + 8192;          // [512][32]  k-major x dup-batch
    float* part  = hd_s + 16384;       // [256][17]
    float* xp_s  = part + 256*17;      // [16][16]
    float* act_s = xp_s + 256;         // [16][16]
    float* c_s   = act_s + 256;        // [4][16]

    const int tid = threadIdx.x;
    const int u0  = blockIdx.x * 4;

    // Load w_hh slice: local gate lg = j*4 + i -> global gate j*512 + u0 + i
    for (int idx = tid; idx < 16*512; idx += 256) {
        int lg = idx >> 9;
        int k  = idx & 511;
        int gate = (lg >> 2) * Hz + u0 + (lg & 3);
        w_s[k*16 + lg] = w_hh[(size_t)gate * Hz + k];
    }
    if (tid < 64) {
        c_s[tid] = 0.f;
        int ul = tid >> 4, b = tid & 15;
        g_h[(u0 + ul)*16 + b] = 0.f;   // h_0 = 0 in buffer 0
    }
    __syncthreads();
    if (tid == 0) {
        __threadfence();
        asm volatile("st.release.gpu.global.u32 [%0], %1;"
                     :: "l"(flags + blockIdx.x), "r"(1u) : "memory");
    }

    const int ks   = tid >> 4;            // 0..15 K-split
    const int tile = tid & 15;
    const int gt4  = (tile >> 2) * 4;     // gate group base
    const int bt4  = (tile & 3) * 4;      // batch group base

    const int xp_lg  = tid >> 4;
    const int xp_b   = tid & 15;
    const size_t xp_off = (size_t)((xp_lg >> 2) * Hz + u0 + (xp_lg & 3));

    for (int t = 0; t < Sz; t++) {
        // prefetch xproj slice for this step (independent of barrier)
        float xp_r = xproj[((size_t)((xp_b << 9) | t)) * Gz + xp_off];

        // wait until all CTAs have published h_t
        if (tid < NCTA) {
            unsigned tgt = (unsigned)(t + 1), v;
            do {
                asm volatile("ld.acquire.gpu.global.u32 %0, [%1];"
                             : "=r"(v) : "l"(flags + tid) : "memory");
            } while (v < tgt);
        }
        __syncthreads();

        // load h_t (L2) into duplicated SMEM layout
        {
            const float4* hg = (const float4*)(g_h + (t & 1) * 8192);
#pragma unroll
            for (int i = 0; i < 8; i++) {
                int o4 = tid + 256*i;            // float4 index
                float4 v = __ldcg(hg + o4);
                float* d = hd_s + 8*o4;
                *(float4*)(d)     = make_float4(v.x, v.x, v.y, v.y);
                *(float4*)(d + 4) = make_float4(v.z, v.z, v.w, v.w);
            }
        }
        xp_s[tid] = xp_r;
        __syncthreads();

        ull acc[8];
#pragma unroll
        for (int i = 0; i < 8; i++) acc[i] = 0ull;

        const int kb = ks * 32;
#pragma unroll
        for (int kk = 0; kk < 32; kk++) {
            int k = kb + kk;
            ulonglong2 wv  = *(const ulonglong2*)(w_s  + k*16 + gt4);       // (g0,g1),(g2,g3)
            ulonglong2 h01 = *(const ulonglong2*)(hd_s + k*32 + 2*bt4);     // (b0,b0),(b1,b1)
            ulonglong2 h23 = *(const ulonglong2*)(hd_s + k*32 + 2*bt4 + 4);
            fma2(acc[0], wv.x, h01.x);
            fma2(acc[1], wv.x, h01.y);
            fma2(acc[2], wv.x, h23.x);
            fma2(acc[3], wv.x, h23.y);
            fma2(acc[4], wv.y, h01.x);
            fma2(acc[5], wv.y, h01.y);
            fma2(acc[6], wv.y, h23.x);
            fma2(acc[7], wv.y, h23.y);
        }
#pragma unroll
        for (int gp = 0; gp < 2; gp++)
#pragma unroll
            for (int bi = 0; bi < 4; bi++) {
                float2 f = *(float2*)&acc[gp*4 + bi];
                int g0 = gt4 + 2*gp, b = bt4 + bi;
                part[(g0*16 + b)*17 + ks]       = f.x;
                part[((g0+1)*16 + b)*17 + ks]   = f.y;
            }
        __syncthreads();

        // reduce K-splits + activation; tid -> (lg = tid/16, b = tid%16)
        {
            float s = xp_s[tid];
#pragma unroll
            for (int q = 0; q < 16; q++) s += part[tid*17 + q];
            int j = tid >> 6;  // 0=i 1=f 2=g 3=o
            float a = (j == 2) ? tanhf(s) : 1.f / (1.f + expf(-s));
            act_s[tid] = a;
        }
        __syncthreads();

        if (tid < 64) {
            int ul = tid >> 4, b = tid & 15;
            float iv = act_s[tid];
            float fv = act_s[tid + 64];
            float gv = act_s[tid + 128];
            float ov = act_s[tid + 192];
            float c = fv * c_s[tid] + iv * gv;
            c_s[tid] = c;
            float h = ov * tanhf(c);
            g_h[((t+1) & 1) * 8192 + (u0 + ul)*16 + b] = h;
            hs[((size_t)((b << 9) | t)) * Hz + u0 + ul] = h;
        }
        __syncthreads();
        if (tid == 0) {
            __threadfence();
            asm volatile("st.release.gpu.global.u32 [%0], %1;"
                         :: "l"(flags + blockIdx.x), "r"((unsigned)(t + 2)) : "memory");
        }
    }
}

// ------------------------------------------------------------------
extern "C" void kernel_launch(void* const* d_in, const int* in_sizes, int n_in,
                              void* d_out, int out_size)
{
    const int*   src   = (const int*)  d_in[0];
    const float* w_emb = (const float*)d_in[1];
    const float* b_emb = (const float*)d_in[2];
    const float* w_ih0 = (const float*)d_in[3];
    const float* w_hh0 = (const float*)d_in[4];
    const float* b_ih0 = (const float*)d_in[5];
    const float* b_hh0 = (const float*)d_in[6];
    const float* w_ih1 = (const float*)d_in[7];
    const float* w_hh1 = (const float*)d_in[8];
    const float* b_ih1 = (const float*)d_in[9];
    const float* b_hh1 = (const float*)d_in[10];
    const float* w1    = (const float*)d_in[11];
    const float* b1    = (const float*)d_in[12];
    const float* w2    = (const float*)d_in[13];
    const float* b2    = (const float*)d_in[14];
    float* out = (float*)d_out;

    float *emb, *xp, *hs0, *hs1, *hid;
    unsigned* flags;
    cudaGetSymbolAddress((void**)&emb, g_emb);
    cudaGetSymbolAddress((void**)&xp,  g_xproj);
    cudaGetSymbolAddress((void**)&hs0, g_hs0);
    cudaGetSymbolAddress((void**)&hs1, g_hs1);
    cudaGetSymbolAddress((void**)&hid, g_hid);
    cudaGetSymbolAddress((void**)&flags, g_flag);

    const int scan_smem = (8192 + 16384 + 256*17 + 256 + 256 + 64) * 4;
    cudaFuncSetAttribute(lstm_scan, cudaFuncAttributeMaxDynamicSharedMemorySize,
                         scan_smem);

    const int M = Bz * Sz;  // 8192

    embed_kernel<<<(M*Hz + 255)/256, 256>>>(src, w_emb, b_emb);
    reset_kernel<<<1, 256>>>();

    gemm_nt<<<dim3(Gz/128, M/128), 256>>>(emb, w_ih0, b_ih0, b_hh0, xp,
                                          M, Gz, Hz, 0);
    lstm_scan<<<NCTA, 256, scan_smem>>>(xp, w_hh0, hs0, flags);

    gemm_nt<<<dim3(Gz/128, M/128), 256>>>(hs0, w_ih1, b_ih1, b_hh1, xp,
                                          M, Gz, Hz, 0);
    lstm_scan<<<NCTA, 256, scan_smem>>>(xp, w_hh1, hs1, flags + NCTA);

    gemm_nt<<<dim3(1, M/128), 256>>>(hs1, w1, b1, nullptr, hid,
                                     M, 128, Hz, 1);

    gemm_nt<<<dim3((Vz + 127)/128, M/128), 256>>>(hid, w2, b2, nullptr, out,
                                                  M, Vz, 128, 0);
}

// round 3
// speedup vs baseline: 2.2017x; 2.2017x over previous
#include <cuda_runtime.h>
#include <cuda_bf16.h>
#include <math.h>

#define Bz 16
#define Sz 512
#define Hz 512
#define Vz 10000
#define Gz 2048
#define NCTA 128

typedef unsigned long long ull;

__device__ __forceinline__ void fma2(ull& d, ull a, ull b) {
    asm("fma.rn.f32x2 %0, %1, %2, %0;" : "+l"(d) : "l"(a), "l"(b));
}

// ---- scratch (static device globals) ----
__device__ float g_emb [Bz*Sz*Hz];
__device__ float g_xproj[Bz*Sz*Gz];
__device__ float g_hs0 [Bz*Sz*Hz];
__device__ float g_hs1 [Bz*Sz*Hz];
__device__ float g_hid [Bz*Sz*128];
__device__ float g_h   [2*Hz*Bz];      // double-buffered h, layout [u][b]
__device__ unsigned g_bar[2];          // grid-barrier counters

// ------------------------------------------------------------------
__global__ void reset_kernel() { g_bar[0] = 0u; g_bar[1] = 0u; }

__global__ void embed_kernel(const int* __restrict__ src,
                             const float* __restrict__ w_emb,
                             const float* __restrict__ b_emb)
{
    int idx = blockIdx.x * 256 + threadIdx.x;
    if (idx >= Bz*Sz*Hz) return;
    int h  = idx & (Hz-1);
    int bs = idx >> 9;
    int v  = src[bs];
    g_emb[idx] = w_emb[h*Vz + v] + b_emb[h];
}

// ------------------------------------------------------------------
// C[M,N] = A[M,K] @ B[N,K]^T + bias (+bias2), optional relu.
// 128x64 tile, BK=16, 8x4 microtile via FFMA2 (A dup'd in SMEM).
// M % 128 == 0, K % 16 == 0, N guarded. N assumed even.
#define ASTR 260
__global__ void __launch_bounds__(256)
gemm_nt(const float* __restrict__ A, const float* __restrict__ B,
        const float* __restrict__ bias, const float* __restrict__ bias2,
        float* __restrict__ C, int M, int N, int K, int relu)
{
    __shared__ float As[16*ASTR];   // [k][2*128] duplicated A
    __shared__ float Bs[16*64];     // [k][64]

    const int n0 = blockIdx.x * 64;
    const int m0 = blockIdx.y * 128;
    const int tid = threadIdx.x;

    // A load map: 64 rows x 2, 4 k-floats each
    const int lr = tid >> 2;          // 0..63
    const int lc = (tid & 3) * 4;     // 0,4,8,12
    const float* Ap0 = A + (size_t)(m0 + lr)      * K + lc;
    const float* Ap1 = A + (size_t)(m0 + lr + 64) * K + lc;

    // B load map: 64 rows, 4 k-floats each
    const int rb = tid & 63;
    const int cb = (tid >> 6) * 4;
    const float* Bp = B + (size_t)(n0 + rb) * K + cb;
    const bool bval = (n0 + rb) < N;

    const int tx = tid & 15;          // n: pairs 2tx and 32+2tx
    const int ty = tid >> 4;          // m: rows 8*ty .. 8*ty+7

    ull acc[8][2];
#pragma unroll
    for (int i = 0; i < 8; i++) { acc[i][0] = 0ull; acc[i][1] = 0ull; }

    for (int kb = 0; kb < K; kb += 16) {
        float4 a0 = *(const float4*)(Ap0 + kb);
        float4 a1 = *(const float4*)(Ap1 + kb);
        float4 b4 = bval ? *(const float4*)(Bp + kb) : make_float4(0,0,0,0);
        __syncthreads();
        {
            float av0[4] = {a0.x, a0.y, a0.z, a0.w};
            float av1[4] = {a1.x, a1.y, a1.z, a1.w};
            float bw [4] = {b4.x, b4.y, b4.z, b4.w};
#pragma unroll
            for (int j = 0; j < 4; j++) {
                float* as = As + (lc + j) * ASTR;
                *(float2*)(as + 2*lr)        = make_float2(av0[j], av0[j]);
                *(float2*)(as + 2*(lr + 64)) = make_float2(av1[j], av1[j]);
                Bs[(cb + j) * 64 + rb] = bw[j];
            }
        }
        __syncthreads();
#pragma unroll
        for (int k = 0; k < 16; k++) {
            const float* as = As + k * ASTR + 16 * ty;
            ulonglong2 a01 = *(const ulonglong2*)(as);
            ulonglong2 a23 = *(const ulonglong2*)(as + 4);
            ulonglong2 a45 = *(const ulonglong2*)(as + 8);
            ulonglong2 a67 = *(const ulonglong2*)(as + 12);
            ull bv0 = *(const ull*)(Bs + k*64 + 2*tx);
            ull bv1 = *(const ull*)(Bs + k*64 + 32 + 2*tx);
            ull av[8] = {a01.x, a01.y, a23.x, a23.y, a45.x, a45.y, a67.x, a67.y};
#pragma unroll
            for (int mi = 0; mi < 8; mi++) {
                fma2(acc[mi][0], av[mi], bv0);
                fma2(acc[mi][1], av[mi], bv1);
            }
        }
    }

    // epilogue: pairs (n_a, n_a+1), (n_b, n_b+1); N even -> pair-valid jointly
    const int n_a = n0 + 2*tx;
    const int n_b = n0 + 32 + 2*tx;
    const bool va = n_a < N, vb = n_b < N;
    float ba0=0.f, ba1=0.f, bb0=0.f, bb1=0.f;
    if (va) {
        ba0 = bias[n_a]   + (bias2 ? bias2[n_a]   : 0.f);
        ba1 = bias[n_a+1] + (bias2 ? bias2[n_a+1] : 0.f);
    }
    if (vb) {
        bb0 = bias[n_b]   + (bias2 ? bias2[n_b]   : 0.f);
        bb1 = bias[n_b+1] + (bias2 ? bias2[n_b+1] : 0.f);
    }
#pragma unroll
    for (int mi = 0; mi < 8; mi++) {
        int m = m0 + 8*ty + mi;
        if (va) {
            float2 f = *(float2*)&acc[mi][0];
            f.x += ba0; f.y += ba1;
            if (relu) { f.x = fmaxf(f.x, 0.f); f.y = fmaxf(f.y, 0.f); }
            *(float2*)(C + (size_t)m * N + n_a) = f;
        }
        if (vb) {
            float2 f = *(float2*)&acc[mi][1];
            f.x += bb0; f.y += bb1;
            if (relu) { f.x = fmaxf(f.x, 0.f); f.y = fmaxf(f.y, 0.f); }
            *(float2*)(C + (size_t)m * N + n_b) = f;
        }
    }
}

// ------------------------------------------------------------------
// Persistent LSTM scan (R1 structure + FFMA2 w-dup inner loop).
__device__ __forceinline__ void grid_barrier(unsigned* ctr, unsigned target)
{
    __syncthreads();
    if (threadIdx.x == 0) {
        __threadfence();
        atomicAdd(ctr, 1u);
        while (*((volatile unsigned*)ctr) < target) { }
    }
    __syncthreads();
}

#define WSTR 36
__global__ void __launch_bounds__(256)
lstm_scan(const float* __restrict__ xproj, const float* __restrict__ w_hh,
          float* __restrict__ hs, unsigned* __restrict__ ctr)
{
    extern __shared__ float sm[];
    float* w_s   = sm;                     // [512][36]  k-major, dup'd gates
    float* h_s   = sm + 512*WSTR;          // [512][16]  k-major x batch
    float* part  = h_s + 8192;             // [256][17]
    float* xp_s  = part + 256*17;          // [16][16]
    float* act_s = xp_s + 256;             // [16][16]
    float* c_s   = act_s + 256;            // [4][16]

    const int tid = threadIdx.x;
    const int u0  = blockIdx.x * 4;

    // Load w_hh slice duplicated: lg = j*4 + i -> gate j*512 + u0 + i
    for (int idx = tid; idx < 16*512; idx += 256) {
        int lg = idx >> 9;
        int k  = idx & 511;
        int gate = (lg >> 2) * Hz + u0 + (lg & 3);
        float w = w_hh[(size_t)gate * Hz + k];
        *(float2*)(w_s + k*WSTR + 2*lg) = make_float2(w, w);
    }
    if (tid < 64) {
        c_s[tid] = 0.f;
        int ul = tid >> 4, b = tid & 15;
        g_h[(u0 + ul)*16 + b] = 0.f;       // h_0 = 0 in buffer 0
    }

    unsigned epoch = 1;
    grid_barrier(ctr, NCTA * epoch);

    const int ks   = tid >> 4;             // 0..15 K-split (strided)
    const int tile = tid & 15;
    const int gt4  = (tile >> 2) * 4;      // gate group base
    const int bt4  = (tile & 3) * 4;       // batch group base

    const int xp_lg = tid >> 4;
    const int xp_b  = tid & 15;
    const size_t xp_off = (size_t)((xp_lg >> 2) * Hz + u0 + (xp_lg & 3));

    for (int t = 0; t < Sz; t++) {
        // prefetch xproj slice (independent of h availability)
        float xp_r = xproj[((size_t)((xp_b << 9) | t)) * Gz + xp_off];

        // load h_t (written by all CTAs last step)
        {
            const float4* hg = (const float4*)(g_h + (t & 1) * 8192);
            float4* hd = (float4*)h_s;
#pragma unroll
            for (int i = 0; i < 8; i++)
                hd[tid + 256*i] = __ldcg(hg + tid + 256*i);
        }
        xp_s[tid] = xp_r;
        __syncthreads();

        ull acc[8];
#pragma unroll
        for (int i = 0; i < 8; i++) acc[i] = 0ull;

#pragma unroll
        for (int kk = 0; kk < 32; kk++) {
            int k = kk*16 + ks;            // strided K-split: bank-disjoint
            ulonglong2 w01 = *(const ulonglong2*)(w_s + k*WSTR + 2*gt4);
            ulonglong2 w23 = *(const ulonglong2*)(w_s + k*WSTR + 2*gt4 + 4);
            ulonglong2 hp  = *(const ulonglong2*)(h_s + k*16 + bt4);
            fma2(acc[0], w01.x, hp.x);     // g0 x (b0,b1)
            fma2(acc[1], w01.x, hp.y);     // g0 x (b2,b3)
            fma2(acc[2], w01.y, hp.x);
            fma2(acc[3], w01.y, hp.y);
            fma2(acc[4], w23.x, hp.x);
            fma2(acc[5], w23.x, hp.y);
            fma2(acc[6], w23.y, hp.x);
            fma2(acc[7], w23.y, hp.y);
        }
#pragma unroll
        for (int g = 0; g < 4; g++)
#pragma unroll
            for (int bp = 0; bp < 2; bp++) {
                float2 f = *(float2*)&acc[g*2 + bp];
                int b = bt4 + 2*bp;
                part[((gt4+g)*16 + b)*17 + ks]     = f.x;
                part[((gt4+g)*16 + b + 1)*17 + ks] = f.y;
            }
        __syncthreads();

        // reduce K-splits + activation
        {
            float s = xp_s[tid];
#pragma unroll
            for (int q = 0; q < 16; q++) s += part[tid*17 + q];
            int j = tid >> 6;  // 0=i 1=f 2=g 3=o
            float a = (j == 2) ? tanhf(s) : 1.f / (1.f + expf(-s));
            act_s[tid] = a;
        }
        __syncthreads();

        if (tid < 64) {
            int ul = tid >> 4, b = tid & 15;
            float iv = act_s[tid];
            float fv = act_s[tid + 64];
            float gv = act_s[tid + 128];
            float ov = act_s[tid + 192];
            float c = fv * c_s[tid] + iv * gv;
            c_s[tid] = c;
            float h = ov * tanhf(c);
            g_h[((t+1) & 1) * 8192 + (u0 + ul)*16 + b] = h;
            hs[((size_t)((b << 9) | t)) * Hz + u0 + ul] = h;
        }
        epoch++;
        grid_barrier(ctr, NCTA * epoch);
    }
}

// ------------------------------------------------------------------
extern "C" void kernel_launch(void* const* d_in, const int* in_sizes, int n_in,
                              void* d_out, int out_size)
{
    const int*   src   = (const int*)  d_in[0];
    const float* w_emb = (const float*)d_in[1];
    const float* b_emb = (const float*)d_in[2];
    const float* w_ih0 = (const float*)d_in[3];
    const float* w_hh0 = (const float*)d_in[4];
    const float* b_ih0 = (const float*)d_in[5];
    const float* b_hh0 = (const float*)d_in[6];
    const float* w_ih1 = (const float*)d_in[7];
    const float* w_hh1 = (const float*)d_in[8];
    const float* b_ih1 = (const float*)d_in[9];
    const float* b_hh1 = (const float*)d_in[10];
    const float* w1    = (const float*)d_in[11];
    const float* b1    = (const float*)d_in[12];
    const float* w2    = (const float*)d_in[13];
    const float* b2    = (const float*)d_in[14];
    float* out = (float*)d_out;

    float *emb, *xp, *hs0, *hs1, *hid;
    unsigned* bar;
    cudaGetSymbolAddress((void**)&emb, g_emb);
    cudaGetSymbolAddress((void**)&xp,  g_xproj);
    cudaGetSymbolAddress((void**)&hs0, g_hs0);
    cudaGetSymbolAddress((void**)&hs1, g_hs1);
    cudaGetSymbolAddress((void**)&hid, g_hid);
    cudaGetSymbolAddress((void**)&bar, g_bar);

    const int scan_smem = (512*WSTR + 8192 + 256*17 + 256 + 256 + 64) * 4;
    cudaFuncSetAttribute(lstm_scan, cudaFuncAttributeMaxDynamicSharedMemorySize,
                         scan_smem);

    const int M = Bz * Sz;  // 8192

    embed_kernel<<<(M*Hz + 255)/256, 256>>>(src, w_emb, b_emb);
    reset_kernel<<<1, 1>>>();

    gemm_nt<<<dim3(Gz/64, M/128), 256>>>(emb, w_ih0, b_ih0, b_hh0, xp,
                                         M, Gz, Hz, 0);
    lstm_scan<<<NCTA, 256, scan_smem>>>(xp, w_hh0, hs0, bar);

    gemm_nt<<<dim3(Gz/64, M/128), 256>>>(hs0, w_ih1, b_ih1, b_hh1, xp,
                                         M, Gz, Hz, 0);
    lstm_scan<<<NCTA, 256, scan_smem>>>(xp, w_hh1, hs1, bar + 1);

    gemm_nt<<<dim3(2, M/128), 256>>>(hs1, w1, b1, nullptr, hid,
                                     M, 128, Hz, 1);

    gemm_nt<<<dim3((Vz + 63)/64, M/128), 256>>>(hid, w2, b2, nullptr, out,
                                                M, Vz, 128, 0);
}

// round 4
// speedup vs baseline: 2.8196x; 1.2806x over previous
#include <cuda_runtime.h>
#include <cuda_bf16.h>
#include <math.h>

#define Bz 16
#define Sz 512
#define Hz 512
#define Vz 10000
#define Gz 2048
#define NCTA 128

// ---- scratch (static device globals) ----
__device__ float g_emb [Bz*Sz*Hz];
__device__ float g_xproj[Bz*Sz*Gz];
__device__ float g_hs0 [Bz*Sz*Hz];
__device__ float g_hs1 [Bz*Sz*Hz];
__device__ float g_hid [Bz*Sz*128];
__device__ float g_h   [2*Hz*Bz];      // double-buffered h, layout [u][b]
__device__ unsigned g_bar[2];          // grid-barrier counters

// ------------------------------------------------------------------
__global__ void reset_kernel() { g_bar[0] = 0u; g_bar[1] = 0u; }

__global__ void embed_kernel(const int* __restrict__ src,
                             const float* __restrict__ w_emb,
                             const float* __restrict__ b_emb)
{
    int idx = blockIdx.x * 256 + threadIdx.x;
    if (idx >= Bz*Sz*Hz) return;
    int h  = idx & (Hz-1);
    int bs = idx >> 9;
    int v  = src[bs];
    g_emb[idx] = w_emb[h*Vz + v] + b_emb[h];
}

// ------------------------------------------------------------------
// tf32 tensor-core GEMM: C[M,N] = A[M,K] @ B[N,K]^T + bias (+bias2), relu opt.
// 128x128 tile, K-chunk 32, 8 warps (2x4), warp = 64x32 via m16n8k8.
// M%128==0, K%32==0, N even; B rows and C cols guarded against N.
__device__ __forceinline__ unsigned f2tf(float f) {
    unsigned u;
    asm("cvt.rna.tf32.f32 %0, %1;" : "=r"(u) : "f"(f));
    return u;
}
__device__ __forceinline__ void mma_tf32(float* d, const unsigned* a,
                                         const unsigned* b) {
    asm("mma.sync.aligned.m16n8k8.row.col.f32.tf32.tf32.f32 "
        "{%0,%1,%2,%3}, {%4,%5,%6,%7}, {%8,%9}, {%0,%1,%2,%3};"
        : "+f"(d[0]), "+f"(d[1]), "+f"(d[2]), "+f"(d[3])
        : "r"(a[0]), "r"(a[1]), "r"(a[2]), "r"(a[3]),
          "r"(b[0]), "r"(b[1]));
}

__global__ void __launch_bounds__(256)
gemm_tf32(const float* __restrict__ A, const float* __restrict__ B,
          const float* __restrict__ bias, const float* __restrict__ bias2,
          float* __restrict__ C, int M, int N, int K, int relu)
{
    // fragment-order SMEM: A [mt(8)][ks(4)][reg(4)][lane(32)], B [nt(16)][ks(4)][reg(2)][lane(32)]
    __shared__ unsigned As[8*4*4*32];
    __shared__ unsigned Bs[16*4*2*32];

    const int tid = threadIdx.x;
    const int n0 = blockIdx.x * 128;
    const int m0 = blockIdx.y * 128;

    // loader map: 2 threads per row, 16 k-floats each
    const int lm = tid >> 1;            // 0..127
    const int lk = (tid & 1) * 16;      // 0 or 16
    const float* Ap = A + (size_t)(m0 + lm) * K + lk;
    const float* Bp = B + (size_t)(n0 + lm) * K + lk;
    const bool bval = (n0 + lm) < N;

    const int warp = tid >> 5;
    const int lane = tid & 31;
    const int wm = warp >> 2;           // 0..1 -> 64 m each
    const int wn = warp & 3;            // 0..3 -> 32 n each

    float acc[4][4][4];
#pragma unroll
    for (int i = 0; i < 4; i++)
#pragma unroll
        for (int j = 0; j < 4; j++)
#pragma unroll
            for (int r = 0; r < 4; r++) acc[i][j][r] = 0.f;

    float4 a_r[4], b_r[4];
    const float4 z4 = make_float4(0.f, 0.f, 0.f, 0.f);

    // prefetch chunk 0
#pragma unroll
    for (int j = 0; j < 4; j++) {
        a_r[j] = *(const float4*)(Ap + 4*j);
        b_r[j] = bval ? *(const float4*)(Bp + 4*j) : z4;
    }

    const int mt_s = lm >> 4, r_s = lm & 15;         // A store coords
    const int nt_s = lm >> 3, ln_s = lm & 7;         // B store coords
    const int nch = K >> 5;

    for (int ch = 0; ch < nch; ch++) {
        __syncthreads();
#pragma unroll
        for (int j = 0; j < 4; j++) {
            int kc = lk + 4*j;                       // chunk-local k (0..28)
            int ks = kc >> 3;
            int cr = (kc & 7) >> 2;                  // 0/1: col half
            uint4 av = make_uint4(f2tf(a_r[j].x), f2tf(a_r[j].y),
                                  f2tf(a_r[j].z), f2tf(a_r[j].w));
            *(uint4*)&As[(((mt_s*4 + ks)*4) + cr*2 + (r_s >> 3))*32 + (r_s & 7)*4] = av;
            uint4 bv = make_uint4(f2tf(b_r[j].x), f2tf(b_r[j].y),
                                  f2tf(b_r[j].z), f2tf(b_r[j].w));
            *(uint4*)&Bs[(((nt_s*4 + ks)*2) + cr)*32 + ln_s*4] = bv;
        }
        __syncthreads();

        if (ch + 1 < nch) {
            const float* ap = Ap + (ch + 1)*32;
            const float* bp = Bp + (ch + 1)*32;
#pragma unroll
            for (int j = 0; j < 4; j++) {
                a_r[j] = *(const float4*)(ap + 4*j);
                b_r[j] = bval ? *(const float4*)(bp + 4*j) : z4;
            }
        }

#pragma unroll
        for (int ks = 0; ks < 4; ks++) {
            unsigned af[4][4];
#pragma unroll
            for (int mi = 0; mi < 4; mi++) {
                int base = (((wm*4 + mi)*4 + ks)*4)*32 + lane;
                af[mi][0] = As[base];
                af[mi][1] = As[base + 32];
                af[mi][2] = As[base + 64];
                af[mi][3] = As[base + 96];
            }
#pragma unroll
            for (int ni = 0; ni < 4; ni++) {
                int bb = (((wn*4 + ni)*4 + ks)*2)*32 + lane;
                unsigned bf[2] = { Bs[bb], Bs[bb + 32] };
#pragma unroll
                for (int mi = 0; mi < 4; mi++)
                    mma_tf32(acc[mi][ni], af[mi], bf);
            }
        }
    }

    // epilogue
    const int g  = lane >> 2;
    const int tg = lane & 3;
#pragma unroll
    for (int ni = 0; ni < 4; ni++) {
        int ncol = n0 + wn*32 + ni*8 + tg*2;
        if (ncol < N) {                              // N even -> pair valid
            float bb0 = bias[ncol]   + (bias2 ? bias2[ncol]   : 0.f);
            float bb1 = bias[ncol+1] + (bias2 ? bias2[ncol+1] : 0.f);
#pragma unroll
            for (int mi = 0; mi < 4; mi++) {
                int mrow = m0 + wm*64 + mi*16 + g;
                float2 v0 = make_float2(acc[mi][ni][0] + bb0,
                                        acc[mi][ni][1] + bb1);
                float2 v1 = make_float2(acc[mi][ni][2] + bb0,
                                        acc[mi][ni][3] + bb1);
                if (relu) {
                    v0.x = fmaxf(v0.x, 0.f); v0.y = fmaxf(v0.y, 0.f);
                    v1.x = fmaxf(v1.x, 0.f); v1.y = fmaxf(v1.y, 0.f);
                }
                *(float2*)(C + (size_t)mrow * N + ncol)       = v0;
                *(float2*)(C + (size_t)(mrow + 8) * N + ncol) = v1;
            }
        }
    }
}

// ------------------------------------------------------------------
// Persistent LSTM scan — exact R1 version (proven 1.79us/step shape).
__device__ __forceinline__ void grid_barrier(unsigned* ctr, unsigned target)
{
    __syncthreads();
    if (threadIdx.x == 0) {
        __threadfence();
        atomicAdd(ctr, 1u);
        while (*((volatile unsigned*)ctr) < target) { }
    }
    __syncthreads();
}

__global__ void __launch_bounds__(256)
lstm_scan(const float* __restrict__ xproj, const float* __restrict__ w_hh,
          float* __restrict__ hs, unsigned* __restrict__ ctr)
{
    extern __shared__ float sm[];
    float* w_s   = sm;                 // [512][16]  k-major x local-gate
    float* h_s   = sm + 8192;          // [512][16]  k-major x batch
    float* part  = sm + 16384;         // [256][17]
    float* xp_s  = part + 256*17;      // [16][16]
    float* act_s = xp_s + 256;         // [16][16]
    float* c_s   = act_s + 256;        // [4][16]

    const int tid = threadIdx.x;
    const int u0  = blockIdx.x * 4;

    for (int idx = tid; idx < 16*512; idx += 256) {
        int lg = idx >> 9;
        int k  = idx & 511;
        int gate = (lg >> 2) * Hz + u0 + (lg & 3);
        w_s[k*16 + lg] = w_hh[(size_t)gate * Hz + k];
    }
    if (tid < 64) {
        c_s[tid] = 0.f;
        int ul = tid >> 4, b = tid & 15;
        g_h[(u0 + ul)*16 + b] = 0.f;
    }

    unsigned epoch = 1;
    grid_barrier(ctr, NCTA * epoch);

    const int ks   = tid >> 4;
    const int tile = tid & 15;
    const int gt4  = (tile >> 2) * 4;
    const int bt4  = (tile & 3) * 4;

    for (int t = 0; t < Sz; t++) {
        {
            int lg = tid >> 4, b = tid & 15;
            int gate = (lg >> 2) * Hz + u0 + (lg & 3);
            xp_s[tid] = xproj[((size_t)((b << 9) | t)) * Gz + gate];
        }
        {
            const float4* hg = (const float4*)(g_h + (t & 1) * 8192);
            float4* hd = (float4*)h_s;
#pragma unroll
            for (int i = 0; i < 8; i++)
                hd[tid + 256*i] = __ldcg(hg + tid + 256*i);
        }
        __syncthreads();

        float acc[4][4];
#pragma unroll
        for (int i = 0; i < 4; i++)
#pragma unroll
            for (int j = 0; j < 4; j++) acc[i][j] = 0.f;

        const int kb = ks * 32;
#pragma unroll
        for (int kk = 0; kk < 32; kk++) {
            int k = kb + kk;
            float4 h4 = *(const float4*)(h_s + k*16 + bt4);
            float4 w4 = *(const float4*)(w_s + k*16 + gt4);
            float hv[4] = {h4.x, h4.y, h4.z, h4.w};
            float wv[4] = {w4.x, w4.y, w4.z, w4.w};
#pragma unroll
            for (int gi = 0; gi < 4; gi++)
#pragma unroll
                for (int bi = 0; bi < 4; bi++)
                    acc[gi][bi] += wv[gi] * hv[bi];
        }
#pragma unroll
        for (int gi = 0; gi < 4; gi++)
#pragma unroll
            for (int bi = 0; bi < 4; bi++)
                part[((gt4+gi)*16 + (bt4+bi))*17 + ks] = acc[gi][bi];
        __syncthreads();

        {
            float s = xp_s[tid];
#pragma unroll
            for (int q = 0; q < 16; q++) s += part[tid*17 + q];
            int j = tid >> 6;
            float a = (j == 2) ? tanhf(s) : 1.f / (1.f + expf(-s));
            act_s[tid] = a;
        }
        __syncthreads();

        if (tid < 64) {
            int ul = tid >> 4, b = tid & 15;
            float iv = act_s[tid];
            float fv = act_s[tid + 64];
            float gv = act_s[tid + 128];
            float ov = act_s[tid + 192];
            float c = fv * c_s[tid] + iv * gv;
            c_s[tid] = c;
            float h = ov * tanhf(c);
            g_h[((t+1) & 1) * 8192 + (u0 + ul)*16 + b] = h;
            hs[((size_t)((b << 9) | t)) * Hz + u0 + ul] = h;
        }
        epoch++;
        grid_barrier(ctr, NCTA * epoch);
    }
}

// ------------------------------------------------------------------
extern "C" void kernel_launch(void* const* d_in, const int* in_sizes, int n_in,
                              void* d_out, int out_size)
{
    const int*   src   = (const int*)  d_in[0];
    const float* w_emb = (const float*)d_in[1];
    const float* b_emb = (const float*)d_in[2];
    const float* w_ih0 = (const float*)d_in[3];
    const float* w_hh0 = (const float*)d_in[4];
    const float* b_ih0 = (const float*)d_in[5];
    const float* b_hh0 = (const float*)d_in[6];
    const float* w_ih1 = (const float*)d_in[7];
    const float* w_hh1 = (const float*)d_in[8];
    const float* b_ih1 = (const float*)d_in[9];
    const float* b_hh1 = (const float*)d_in[10];
    const float* w1    = (const float*)d_in[11];
    const float* b1    = (const float*)d_in[12];
    const float* w2    = (const float*)d_in[13];
    const float* b2    = (const float*)d_in[14];
    float* out = (float*)d_out;

    float *emb, *xp, *hs0, *hs1, *hid;
    unsigned* bar;
    cudaGetSymbolAddress((void**)&emb, g_emb);
    cudaGetSymbolAddress((void**)&xp,  g_xproj);
    cudaGetSymbolAddress((void**)&hs0, g_hs0);
    cudaGetSymbolAddress((void**)&hs1, g_hs1);
    cudaGetSymbolAddress((void**)&hid, g_hid);
    cudaGetSymbolAddress((void**)&bar, g_bar);

    const int scan_smem = (8192 + 8192 + 256*17 + 256 + 256 + 64) * 4;
    cudaFuncSetAttribute(lstm_scan, cudaFuncAttributeMaxDynamicSharedMemorySize,
                         scan_smem);

    const int M = Bz * Sz;  // 8192

    embed_kernel<<<(M*Hz + 255)/256, 256>>>(src, w_emb, b_emb);
    reset_kernel<<<1, 1>>>();

    gemm_tf32<<<dim3(Gz/128, M/128), 256>>>(emb, w_ih0, b_ih0, b_hh0, xp,
                                            M, Gz, Hz, 0);
    lstm_scan<<<NCTA, 256, scan_smem>>>(xp, w_hh0, hs0, bar);

    gemm_tf32<<<dim3(Gz/128, M/128), 256>>>(hs0, w_ih1, b_ih1, b_hh1, xp,
                                            M, Gz, Hz, 0);
    lstm_scan<<<NCTA, 256, scan_smem>>>(xp, w_hh1, hs1, bar + 1);

    gemm_tf32<<<dim3(1, M/128), 256>>>(hs1, w1, b1, nullptr, hid,
                                       M, 128, Hz, 1);

    gemm_tf32<<<dim3((Vz + 127)/128, M/128), 256>>>(hid, w2, b2, nullptr, out,
                                                    M, Vz, 128, 0);
}